// round 9
// baseline (speedup 1.0000x reference)
#include <cuda_runtime.h>
#include <cuda_bf16.h>
#include <cstdint>

// Problem constants (fixed by the reference):
//   N_NODES = 100000, IN_F = 256, OUT_F = 128, N_EDGES = 1600000
// Inputs (metadata order): X_input[f32 N*256], adj_row[i32 E], adj_col[i32 E],
//                          adj_val[f32 E], W[f32 256*128], bias[f32 128]
// Output: f32 [N, 128]

#define MAX_NODES 100000
#define IN_F      256
#define OUT_F     128

// Scratch for support = X @ W  (51.2 MB). Static __device__ per harness rules.
__device__ __align__(16) float g_support[(size_t)MAX_NODES * OUT_F];

// ---------------------------------------------------------------------------
// Kernel 1: SGEMM  S[M,128] = X[M,256] @ W[256,128]
// Block tile 128x128, K-step 16, 256 threads, 8x8 register micro-tile.
// FFMA-pipe-bound: predicted ~110-125 us.
// ---------------------------------------------------------------------------
#define BM 128
#define BN 128
#define BK 16
#define TM 8
#define TN 8

__global__ __launch_bounds__(256, 2)
void gemm_kernel(const float* __restrict__ X, const float* __restrict__ W,
                 float* __restrict__ S, int M) {
    __shared__ float As[BK][BM + 4];   // A stored K-major (transposed), padded
    __shared__ float Bs[BK][BN];

    const int tid  = threadIdx.x;
    const int row0 = blockIdx.x * BM;

    const int tcol = tid % (BN / TN);  // 0..15
    const int trow = tid / (BN / TN);  // 0..15

    float acc[TM][TN];
#pragma unroll
    for (int i = 0; i < TM; i++)
#pragma unroll
        for (int j = 0; j < TN; j++) acc[i][j] = 0.0f;

    for (int k0 = 0; k0 < IN_F; k0 += BK) {
        // ---- load A tile: 128 rows x 16 cols = 512 float4, 2 per thread ----
#pragma unroll
        for (int i = 0; i < 2; i++) {
            int f   = tid + i * 256;        // float4 index in tile
            int ar  = f >> 2;               // tile row 0..127
            int ac4 = f & 3;                // float4 within row 0..3
            int grow = row0 + ar;
            if (grow >= M) grow = M - 1;    // clamp: duplicate load, never stored
            float4 v = *(const float4*)(X + (size_t)grow * IN_F + k0 + ac4 * 4);
            As[ac4 * 4 + 0][ar] = v.x;
            As[ac4 * 4 + 1][ar] = v.y;
            As[ac4 * 4 + 2][ar] = v.z;
            As[ac4 * 4 + 3][ar] = v.w;
        }
        // ---- load B tile: 16 rows x 128 cols = 512 float4, 2 per thread ----
#pragma unroll
        for (int i = 0; i < 2; i++) {
            int f   = tid + i * 256;
            int br  = f >> 5;               // 0..15
            int bc4 = f & 31;               // 0..31
            float4 v = *(const float4*)(W + (size_t)(k0 + br) * OUT_F + bc4 * 4);
            *(float4*)&Bs[br][bc4 * 4] = v;
        }
        __syncthreads();

#pragma unroll
        for (int k = 0; k < BK; k++) {
            float a_frag[TM], b_frag[TN];
#pragma unroll
            for (int i = 0; i < TM; i++) a_frag[i] = As[k][trow * TM + i];
#pragma unroll
            for (int j = 0; j < TN; j++) b_frag[j] = Bs[k][tcol * TN + j];
#pragma unroll
            for (int i = 0; i < TM; i++)
#pragma unroll
                for (int j = 0; j < TN; j++)
                    acc[i][j] = fmaf(a_frag[i], b_frag[j], acc[i][j]);
        }
        __syncthreads();
    }

    // ---- store 8x8 micro-tile (two float4 per row) ----
#pragma unroll
    for (int i = 0; i < TM; i++) {
        int r = row0 + trow * TM + i;
        if (r < M) {
            float4 o0 = make_float4(acc[i][0], acc[i][1], acc[i][2], acc[i][3]);
            float4 o1 = make_float4(acc[i][4], acc[i][5], acc[i][6], acc[i][7]);
            float* dst = S + (size_t)r * OUT_F + tcol * TN;
            *(float4*)(dst + 0) = o0;
            *(float4*)(dst + 4) = o1;
        }
    }
}

// ---------------------------------------------------------------------------
// Kernel 2: out[n, :] = bias  (broadcast init; out is poisoned by harness)
// One float4 per thread; column-of-four = idx & 31. ~8 us (HBM write).
// ---------------------------------------------------------------------------
__global__ __launch_bounds__(256)
void init_out_kernel(float* __restrict__ out, const float* __restrict__ bias,
                     int n4) {
    int i = blockIdx.x * blockDim.x + threadIdx.x;
    if (i < n4) {
        float4 b = __ldg((const float4*)bias + (i & 31));
        ((float4*)out)[i] = b;
    }
}

// ---------------------------------------------------------------------------
// Kernel 3: COO SpMM with vector reductions.
// One warp per edge: 32 lanes x float4 = 128 floats (one full row).
// 4 edges per warp iteration -> MLP=4 on gathers; support (51.2 MB) is
// L2-resident so gathers are L2 hits. red.global.add.v4.f32 = no-return
// atomic, 1 op per 16 bytes. LTS-bound: predicted ~130 us.
// ---------------------------------------------------------------------------
#define EDGES_PER_WARP 4

__global__ __launch_bounds__(256)
void spmm_kernel(const int* __restrict__ adj_row, const int* __restrict__ adj_col,
                 const float* __restrict__ adj_val, const float* __restrict__ S,
                 float* __restrict__ out, int E) {
    const int warp_id = (blockIdx.x * blockDim.x + threadIdx.x) >> 5;
    const int lane    = threadIdx.x & 31;
    const int e0      = warp_id * EDGES_PER_WARP;
    if (e0 >= E) return;

    int    r[EDGES_PER_WARP];
    float4 m[EDGES_PER_WARP];

    // Gather phase: issue all loads first (front-batched -> MLP).
#pragma unroll
    for (int i = 0; i < EDGES_PER_WARP; i++) {
        int e = e0 + i;
        if (e < E) {
            int   c = __ldg(adj_col + e);
            float v = __ldg(adj_val + e);
            r[i] = __ldg(adj_row + e);
            float4 s = __ldg((const float4*)(S + (size_t)c * OUT_F) + lane);
            s.x *= v; s.y *= v; s.z *= v; s.w *= v;
            m[i] = s;
        }
    }

    // Scatter phase: no-return vector atomics.
#pragma unroll
    for (int i = 0; i < EDGES_PER_WARP; i++) {
        if (e0 + i < E) {
            float* dst = out + (size_t)r[i] * OUT_F + lane * 4;
            asm volatile("red.global.add.v4.f32 [%0], {%1, %2, %3, %4};"
                         :: "l"(dst), "f"(m[i].x), "f"(m[i].y),
                            "f"(m[i].z), "f"(m[i].w)
                         : "memory");
        }
    }
}

// ---------------------------------------------------------------------------
// Launch: gemm -> init -> spmm (stream-ordered dependencies).
// ---------------------------------------------------------------------------
extern "C" void kernel_launch(void* const* d_in, const int* in_sizes, int n_in,
                              void* d_out, int out_size) {
    const float* X    = (const float*)d_in[0];
    const int*   arow = (const int*)  d_in[1];
    const int*   acol = (const int*)  d_in[2];
    const float* aval = (const float*)d_in[3];
    const float* W    = (const float*)d_in[4];
    const float* bias = (const float*)d_in[5];
    float*       out  = (float*)d_out;

    const int M = in_sizes[0] / IN_F;   // 100000
    const int E = in_sizes[1];          // 1600000

    // One-time symbol lookup (host-side query, not captured, not an alloc).
    static float* S = nullptr;
    if (S == nullptr) {
        void* p = nullptr;
        cudaGetSymbolAddress(&p, g_support);
        S = (float*)p;
    }

    // 1) support = X @ W
    gemm_kernel<<<(M + BM - 1) / BM, 256>>>(X, W, S, M);

    // 2) out = bias (broadcast) — independent of (1), same stream so ordered
    const int n4 = M * (OUT_F / 4);
    init_out_kernel<<<(n4 + 255) / 256, 256>>>(out, bias, n4);

    // 3) out[r] += val * support[c]
    const int nwarps  = (E + EDGES_PER_WARP - 1) / EDGES_PER_WARP;
    const int nblocks = (nwarps + 7) / 8;   // 8 warps / 256-thread block
    spmm_kernel<<<nblocks, 256>>>(arow, acol, aval, S, out, E);
}